// round 2
// baseline (speedup 1.0000x reference)
#include <cuda_runtime.h>

#define ALPHA 26
#define TPB   256           // threads per block == tokens per block
#define SEQ   8192          // S (power of two)

__global__ __launch_bounds__(TPB)
void rotor_kernel(const float* __restrict__ x,
                  const float* __restrict__ rotor,
                  float* __restrict__ out)
{
    __shared__ __align__(16) float s_buf[TPB * ALPHA];   // 26624 B staging, 16B aligned
    __shared__ float s_rn[ALPHA][ALPHA + 2];             // padded vs bank conflicts
    __shared__ float s_inv[ALPHA];

    const int tid = threadIdx.x;

    // --- normalize rotor rows into smem (redundant per block; trivial cost) ---
    if (tid < ALPHA) {
        float ss = 0.f;
        #pragma unroll
        for (int j = 0; j < ALPHA; ++j) {
            float v = rotor[tid * ALPHA + j];
            ss = fmaf(v, v, ss);
        }
        s_inv[tid] = rsqrtf(ss);
    }
    __syncthreads();
    for (int e = tid; e < ALPHA * ALPHA; e += TPB) {
        int r = e / ALPHA;
        s_rn[r][e - r * ALPHA] = rotor[e] * s_inv[r];
    }

    // --- coalesced float4 stage-in of this block's 256 tokens ---
    const size_t base = (size_t)blockIdx.x * (TPB * ALPHA);
    const float4* __restrict__ xin4 = (const float4*)(x + base);
    float4* buf4 = (float4*)s_buf;
    const int n4 = TPB * ALPHA / 4;               // 1664
    #pragma unroll 2
    for (int e = tid; e < n4; e += TPB) buf4[e] = xin4[e];
    __syncthreads();

    // --- per-thread token: rotated 1x26 @ 26x26 + softmax ---
    const int t     = blockIdx.x * TPB + tid;     // linear token id
    const int s     = t & (SEQ - 1);              // sequence position
    const int shift = s % ALPHA;                  // position==1 shift

    float acc[ALPHA];
    #pragma unroll
    for (int j = 0; j < ALPHA; ++j) acc[j] = 0.f;

    #pragma unroll
    for (int i = 0; i < ALPHA; ++i) {
        float xv = s_buf[tid * ALPHA + i];
        int row = i + shift;
        if (row >= ALPHA) row -= ALPHA;
        #pragma unroll
        for (int j = 0; j < ALPHA; ++j)
            acc[j] = fmaf(xv, s_rn[row][j], acc[j]);
    }

    // stable softmax over 26
    float mx = acc[0];
    #pragma unroll
    for (int j = 1; j < ALPHA; ++j) mx = fmaxf(mx, acc[j]);
    float sum = 0.f;
    #pragma unroll
    for (int j = 0; j < ALPHA; ++j) {
        acc[j] = __expf(acc[j] - mx);
        sum += acc[j];
    }
    const float inv = __fdividef(1.0f, sum);

    __syncthreads();                              // done reading s_buf as input
    #pragma unroll
    for (int j = 0; j < ALPHA; ++j)
        s_buf[tid * ALPHA + j] = acc[j] * inv;
    __syncthreads();

    // --- coalesced float4 stage-out ---
    float4* __restrict__ out4 = (float4*)(out + base);
    #pragma unroll 2
    for (int e = tid; e < n4; e += TPB) out4[e] = buf4[e];
}

extern "C" void kernel_launch(void* const* d_in, const int* in_sizes, int n_in,
                              void* d_out, int out_size)
{
    const float* x     = (const float*)d_in[0];   // [128, 8192, 26] f32
    const float* rotor = (const float*)d_in[1];   // [26, 26] f32
    float* out         = (float*)d_out;

    const int total_tokens = out_size / ALPHA;    // 1,048,576
    const int blocks = total_tokens / TPB;        // 4096
    rotor_kernel<<<blocks, TPB>>>(x, rotor, out);
}

// round 3
// speedup vs baseline: 1.7483x; 1.7483x over previous
#include <cuda_runtime.h>

#define ALPHA 26
#define TPB   256           // threads per block == tokens per block
#define SEQ   8192          // S (power of two)

__global__ __launch_bounds__(TPB)
void rotor_kernel(const float* __restrict__ x,
                  const float* __restrict__ rotor,
                  float* __restrict__ out)
{
    __shared__ __align__(16) float s_buf[TPB * ALPHA];   // 26624 B staging
    __shared__ __align__(16) float s_rn[ALPHA][ALPHA + 2]; // 28-float rows (112B, 16B-aligned)
    __shared__ float s_inv[ALPHA];

    const int tid = threadIdx.x;

    // --- normalize rotor rows into smem ---
    if (tid < ALPHA) {
        float ss = 0.f;
        #pragma unroll
        for (int j = 0; j < ALPHA; ++j) {
            float v = rotor[tid * ALPHA + j];
            ss = fmaf(v, v, ss);
        }
        s_inv[tid] = rsqrtf(ss);
    }
    __syncthreads();
    for (int e = tid; e < ALPHA * ALPHA; e += TPB) {
        int r = e / ALPHA;
        s_rn[r][e - r * ALPHA] = rotor[e] * s_inv[r];
    }

    // --- coalesced float4 stage-in of this block's 256 tokens ---
    const size_t base = (size_t)blockIdx.x * (TPB * ALPHA);
    const float4* __restrict__ xin4 = (const float4*)(x + base);
    float4* buf4 = (float4*)s_buf;
    const int n4 = TPB * ALPHA / 4;               // 1664
    #pragma unroll 2
    for (int e = tid; e < n4; e += TPB) buf4[e] = xin4[e];
    __syncthreads();

    // --- per-thread token: rotated-input 1x26 @ 26x26 (uniform rn reads) ---
    const int t     = blockIdx.x * TPB + tid;     // linear token id
    const int s     = t & (SEQ - 1);              // sequence position
    const int shift = s % ALPHA;                  // position==1 shift

    // acc as 13 packed f32x2 pairs (zero bit pattern == {0.f, 0.f})
    unsigned long long acc[ALPHA / 2];
    #pragma unroll
    for (int p = 0; p < ALPHA / 2; ++p) acc[p] = 0ull;

    const float* __restrict__ xrow = s_buf + tid * ALPHA;

    #pragma unroll
    for (int r = 0; r < ALPHA; ++r) {
        int idx = r - shift;
        idx += (idx >> 31) & ALPHA;               // branchless mod 26
        float xv = xrow[idx];                     // per-lane LDS (mild conflicts)
        unsigned long long xx;
        asm("mov.b64 %0, {%1, %1};" : "=l"(xx) : "f"(xv));
        // warp-uniform broadcast reads of rn row r, 13 x 8B
        const unsigned long long* __restrict__ rrow =
            (const unsigned long long*)(&s_rn[r][0]);
        #pragma unroll
        for (int p = 0; p < ALPHA / 2; ++p) {
            unsigned long long bb = rrow[p];
            asm("fma.rn.f32x2 %0, %1, %2, %0;" : "+l"(acc[p]) : "l"(bb), "l"(xx));
        }
    }

    // unpack
    float v[ALPHA];
    #pragma unroll
    for (int p = 0; p < ALPHA / 2; ++p)
        asm("mov.b64 {%0, %1}, %2;" : "=f"(v[2 * p]), "=f"(v[2 * p + 1]) : "l"(acc[p]));

    // stable softmax over 26
    float mx = v[0];
    #pragma unroll
    for (int j = 1; j < ALPHA; ++j) mx = fmaxf(mx, v[j]);
    float sum = 0.f;
    #pragma unroll
    for (int j = 0; j < ALPHA; ++j) {
        v[j] = __expf(v[j] - mx);
        sum += v[j];
    }
    const float inv = __fdividef(1.0f, sum);

    __syncthreads();                              // done reading s_buf as input
    #pragma unroll
    for (int j = 0; j < ALPHA; ++j)
        s_buf[tid * ALPHA + j] = v[j] * inv;
    __syncthreads();

    // --- coalesced float4 stage-out ---
    float4* __restrict__ out4 = (float4*)(out + base);
    #pragma unroll 2
    for (int e = tid; e < n4; e += TPB) out4[e] = buf4[e];
}

extern "C" void kernel_launch(void* const* d_in, const int* in_sizes, int n_in,
                              void* d_out, int out_size)
{
    const float* x     = (const float*)d_in[0];   // [128, 8192, 26] f32
    const float* rotor = (const float*)d_in[1];   // [26, 26] f32
    float* out         = (float*)d_out;

    const int total_tokens = out_size / ALPHA;    // 1,048,576
    const int blocks = total_tokens / TPB;        // 4096
    rotor_kernel<<<blocks, TPB>>>(x, rotor, out);
}

// round 4
// speedup vs baseline: 2.3752x; 1.3586x over previous
#include <cuda_runtime.h>

#define ALPHA 26
#define TPB   128           // threads per block
#define TOKB  256           // tokens per block (2 per thread)
#define SEQ   8192

__global__ __launch_bounds__(TPB, 6)
void rotor_kernel(const float* __restrict__ x,
                  const float* __restrict__ rotor,
                  float* __restrict__ out)
{
    __shared__ __align__(16) float s_buf[TOKB * ALPHA];     // 26624 B
    __shared__ __align__(16) float s_rn[ALPHA][ALPHA + 2];  // 28-float rows, 112B stride
    __shared__ float s_inv[ALPHA];

    const int tid = threadIdx.x;

    // --- normalize rotor rows into smem ---
    if (tid < ALPHA) {
        float ss = 0.f;
        #pragma unroll
        for (int j = 0; j < ALPHA; ++j) {
            float v = rotor[tid * ALPHA + j];
            ss = fmaf(v, v, ss);
        }
        s_inv[tid] = rsqrtf(ss);
    }
    __syncthreads();
    for (int e = tid; e < ALPHA * ALPHA; e += TPB) {
        int r = e / ALPHA;
        s_rn[r][e - r * ALPHA] = rotor[e] * s_inv[r];
    }

    // --- coalesced float4 stage-in of this block's 256 tokens ---
    const size_t base = (size_t)blockIdx.x * (TOKB * ALPHA);
    const float4* __restrict__ xin4 = (const float4*)(x + base);
    float4* buf4 = (float4*)s_buf;
    const int n4 = TOKB * ALPHA / 4;                 // 1664
    #pragma unroll
    for (int e = tid; e < n4; e += TPB) buf4[e] = xin4[e];
    __syncthreads();

    // --- two tokens per thread ---
    const int t0 = blockIdx.x * TOKB + tid;          // token 0
    const int t1 = t0 + TPB;                         // token 1
    const int shift0 = (t0 & (SEQ - 1)) % ALPHA;
    const int shift1 = (t1 & (SEQ - 1)) % ALPHA;

    const float* __restrict__ xr0 = s_buf + tid * ALPHA;
    const float* __restrict__ xr1 = s_buf + (tid + TPB) * ALPHA;

    unsigned long long acc0[13], acc1[13];
    #pragma unroll
    for (int p = 0; p < 13; ++p) { acc0[p] = 0ull; acc1[p] = 0ull; }

    #pragma unroll
    for (int r = 0; r < ALPHA; ++r) {
        int i0 = r - shift0; i0 += (i0 >> 31) & ALPHA;
        int i1 = r - shift1; i1 += (i1 >> 31) & ALPHA;
        float xv0 = xr0[i0];
        float xv1 = xr1[i1];
        unsigned long long xx0, xx1;
        asm("mov.b64 %0, {%1, %1};" : "=l"(xx0) : "f"(xv0));
        asm("mov.b64 %0, {%1, %1};" : "=l"(xx1) : "f"(xv1));

        const float4* __restrict__ rr4 = (const float4*)(&s_rn[r][0]);
        #pragma unroll
        for (int c = 0; c < 6; ++c) {                // cols 0..23
            float4 f = rr4[c];                       // uniform LDS.128 (broadcast)
            unsigned long long b01, b23;
            asm("mov.b64 %0, {%1, %2};" : "=l"(b01) : "f"(f.x), "f"(f.y));
            asm("mov.b64 %0, {%1, %2};" : "=l"(b23) : "f"(f.z), "f"(f.w));
            asm("fma.rn.f32x2 %0, %1, %2, %0;" : "+l"(acc0[2*c  ]) : "l"(b01), "l"(xx0));
            asm("fma.rn.f32x2 %0, %1, %2, %0;" : "+l"(acc0[2*c+1]) : "l"(b23), "l"(xx0));
            asm("fma.rn.f32x2 %0, %1, %2, %0;" : "+l"(acc1[2*c  ]) : "l"(b01), "l"(xx1));
            asm("fma.rn.f32x2 %0, %1, %2, %0;" : "+l"(acc1[2*c+1]) : "l"(b23), "l"(xx1));
        }
        {                                            // cols 24,25
            float2 f = *(const float2*)(&s_rn[r][24]);   // uniform LDS.64
            unsigned long long b;
            asm("mov.b64 %0, {%1, %2};" : "=l"(b) : "f"(f.x), "f"(f.y));
            asm("fma.rn.f32x2 %0, %1, %2, %0;" : "+l"(acc0[12]) : "l"(b), "l"(xx0));
            asm("fma.rn.f32x2 %0, %1, %2, %0;" : "+l"(acc1[12]) : "l"(b), "l"(xx1));
        }
    }

    // --- softmax per token, then write back to s_buf as float2 ---
    float v0[ALPHA], v1[ALPHA];
    #pragma unroll
    for (int p = 0; p < 13; ++p) {
        asm("mov.b64 {%0, %1}, %2;" : "=f"(v0[2*p]), "=f"(v0[2*p+1]) : "l"(acc0[p]));
        asm("mov.b64 {%0, %1}, %2;" : "=f"(v1[2*p]), "=f"(v1[2*p+1]) : "l"(acc1[p]));
    }

    float mx0 = v0[0], mx1 = v1[0];
    #pragma unroll
    for (int j = 1; j < ALPHA; ++j) { mx0 = fmaxf(mx0, v0[j]); mx1 = fmaxf(mx1, v1[j]); }
    float sm0 = 0.f, sm1 = 0.f;
    #pragma unroll
    for (int j = 0; j < ALPHA; ++j) {
        v0[j] = __expf(v0[j] - mx0); sm0 += v0[j];
        v1[j] = __expf(v1[j] - mx1); sm1 += v1[j];
    }
    const float in0 = __fdividef(1.0f, sm0);
    const float in1 = __fdividef(1.0f, sm1);

    __syncthreads();                                 // done reading s_buf
    float2* w0 = (float2*)(s_buf + tid * ALPHA);           // token stride 26 words -> 8B aligned
    float2* w1 = (float2*)(s_buf + (tid + TPB) * ALPHA);
    #pragma unroll
    for (int p = 0; p < 13; ++p) {
        w0[p] = make_float2(v0[2*p] * in0, v0[2*p+1] * in0);
        w1[p] = make_float2(v1[2*p] * in1, v1[2*p+1] * in1);
    }
    __syncthreads();

    // --- coalesced float4 stage-out ---
    float4* __restrict__ out4 = (float4*)(out + base);
    #pragma unroll
    for (int e = tid; e < n4; e += TPB) out4[e] = buf4[e];
}

extern "C" void kernel_launch(void* const* d_in, const int* in_sizes, int n_in,
                              void* d_out, int out_size)
{
    const float* x     = (const float*)d_in[0];   // [128, 8192, 26] f32
    const float* rotor = (const float*)d_in[1];   // [26, 26] f32
    float* out         = (float*)d_out;

    const int total_tokens = out_size / ALPHA;    // 1,048,576
    const int blocks = total_tokens / TOKB;       // 4096
    rotor_kernel<<<blocks, TPB>>>(x, rotor, out);
}